// round 5
// baseline (speedup 1.0000x reference)
#include <cuda_runtime.h>
#include <cstdint>

// SelMaxPool, bin + channel-phased gather:
//   pooled[m][c] = max( max_{j<pool} x[m*pool+j][c],
//                       max_{e active, dst[e]/pool == m} x[src[e]][c] )
// Pass 1 bins active edges' src ids per destination cluster (1 small atomic
// per active edge). Pass 2/3: one warp per cluster gathers & max-reduces,
// split into two channel halves so each phase's working set (~100MB) fits L2
// and the random row gathers become L2 hits.
// Scratch counters are re-zeroed by the last phase (graph-replay safe:
// static zero-init covers the first call). Bin overflow (probability ~0,
// but handled) is scanned in-warp by the owning cluster — no atomics on out.

#define CH 64                 // channels
#define HALF 32               // channels per phase
#define M_MAX 131072          // max clusters supported by static scratch
#define CAP 64                // bin capacity per cluster (E[load] ~= 14)
#define OVF_CAP 131072

__device__ int g_cnt[M_MAX];
__device__ int g_bins[(size_t)M_MAX * CAP];
__device__ int g_ovf_cnt;
__device__ int g_ovf[2 * OVF_CAP];
__device__ unsigned g_done;

__device__ __forceinline__ void atomicMaxFloat(float* addr, float val) {
    if (val >= 0.0f) atomicMax((int*)addr, __float_as_int(val));
    else             atomicMin((unsigned int*)addr, __float_as_uint(val));
}

__device__ __forceinline__ void bin_one(int s, int d, int se, int thresh,
                                        int pool, int sh) {
    if (se >= thresh) return;
    int c = (sh >= 0) ? (d >> sh) : (d / pool);
    int slot = atomicAdd(&g_cnt[c], 1);
    if (slot < CAP) {
        g_bins[(size_t)c * CAP + slot] = s;
    } else {
        int o = atomicAdd(&g_ovf_cnt, 1);
        if (o < OVF_CAP) { g_ovf[2 * o] = s; g_ovf[2 * o + 1] = c; }
    }
}

__global__ void bin_edges_vec_kernel(const int* __restrict__ src,
                                     const int* __restrict__ dst,
                                     const int* __restrict__ sel,
                                     const int* __restrict__ ks_ptr,
                                     int E, int pool, int sh) {
    int t = blockIdx.x * blockDim.x + threadIdx.x;
    int base = t * 4;
    if (base >= E) return;
    int k = ks_ptr[0];
    int thresh = k * k;
    int4 s4 = *(const int4*)(sel + base);
    int4 a4 = *(const int4*)(src + base);
    int4 d4 = *(const int4*)(dst + base);
    bin_one(a4.x, d4.x, s4.x, thresh, pool, sh);
    bin_one(a4.y, d4.y, s4.y, thresh, pool, sh);
    bin_one(a4.z, d4.z, s4.z, thresh, pool, sh);
    bin_one(a4.w, d4.w, s4.w, thresh, pool, sh);
}

__global__ void bin_edges_scalar_kernel(const int* __restrict__ src,
                                        const int* __restrict__ dst,
                                        const int* __restrict__ sel,
                                        const int* __restrict__ ks_ptr,
                                        int E, int pool, int sh) {
    int e = blockIdx.x * blockDim.x + threadIdx.x;
    if (e >= E) return;
    int k = ks_ptr[0];
    bin_one(src[e], dst[e], sel[e], k * k, pool, sh);
}

// Max-reduce a chunk of up to n (<=32) src ids held in register b across the
// warp; lane owns one float of the half-row. 8-way MLP on the random gathers.
__device__ __forceinline__ float gather_chunk(const float* __restrict__ x,
                                              int off_lane, int b, int n,
                                              float acc) {
    const unsigned FULL = 0xffffffffu;
    int i = 0;
    for (; i + 8 <= n; i += 8) {
        int s0 = __shfl_sync(FULL, b, i);
        int s1 = __shfl_sync(FULL, b, i + 1);
        int s2 = __shfl_sync(FULL, b, i + 2);
        int s3 = __shfl_sync(FULL, b, i + 3);
        int s4 = __shfl_sync(FULL, b, i + 4);
        int s5 = __shfl_sync(FULL, b, i + 5);
        int s6 = __shfl_sync(FULL, b, i + 6);
        int s7 = __shfl_sync(FULL, b, i + 7);
        float v0 = __ldg(x + (size_t)s0 * CH + off_lane);
        float v1 = __ldg(x + (size_t)s1 * CH + off_lane);
        float v2 = __ldg(x + (size_t)s2 * CH + off_lane);
        float v3 = __ldg(x + (size_t)s3 * CH + off_lane);
        float v4 = __ldg(x + (size_t)s4 * CH + off_lane);
        float v5 = __ldg(x + (size_t)s5 * CH + off_lane);
        float v6 = __ldg(x + (size_t)s6 * CH + off_lane);
        float v7 = __ldg(x + (size_t)s7 * CH + off_lane);
        float m0 = fmaxf(fmaxf(v0, v1), fmaxf(v2, v3));
        float m1 = fmaxf(fmaxf(v4, v5), fmaxf(v6, v7));
        acc = fmaxf(acc, fmaxf(m0, m1));
    }
    for (; i < n; i++) {
        int s0 = __shfl_sync(FULL, b, i);
        acc = fmaxf(acc, __ldg(x + (size_t)s0 * CH + off_lane));
    }
    return acc;
}

// One warp per cluster, one channel half per launch (off = 0 or HALF).
// zero_pass=1 (second phase) re-zeroes scratch for the next graph replay.
__global__ void gather_half_kernel(const float* __restrict__ x,
                                   float* __restrict__ out,
                                   int M, int pool, int off, int zero_pass) {
    int warp = (blockIdx.x * blockDim.x + threadIdx.x) >> 5;
    int lane = threadIdx.x & 31;

    if (warp < M) {
        int ol = off + lane;
        // Own rows: sequential across warps -> coalesced stream of x-half.
        const float* xb = x + (size_t)warp * pool * CH + ol;
        float acc = __ldg(xb);
        for (int j = 1; j < pool; j++)
            acc = fmaxf(acc, __ldg(xb + (size_t)j * CH));

        int cnt = g_cnt[warp];
        if (zero_pass && lane == 0) g_cnt[warp] = 0;
        if (cnt > CAP) cnt = CAP;

        size_t bb = (size_t)warp * CAP;
        int b0 = (lane < cnt)      ? g_bins[bb + lane]      : 0;
        int b1 = (lane + 32 < cnt) ? g_bins[bb + lane + 32] : 0;
        int n0 = cnt < 32 ? cnt : 32;
        acc = gather_chunk(x, ol, b0, n0, acc);
        if (cnt > 32) acc = gather_chunk(x, ol, b1, cnt - 32, acc);

        // Overflow (normally empty): each warp picks up its own entries.
        int novf = g_ovf_cnt;
        if (novf > OVF_CAP) novf = OVF_CAP;
        for (int i = 0; i < novf; i++) {
            if (g_ovf[2 * i + 1] == warp) {
                int s = g_ovf[2 * i];
                acc = fmaxf(acc, __ldg(x + (size_t)s * CH + ol));
            }
        }

        out[(size_t)warp * CH + ol] = acc;
    }

    if (zero_pass) {
        __syncthreads();
        if (threadIdx.x == 0) {
            __threadfence();
            unsigned t = atomicAdd(&g_done, 1);
            if (t == gridDim.x - 1) {
                g_ovf_cnt = 0;
                g_done = 0;
                __threadfence();
            }
        }
    }
}

// ---- Fallback (M > M_MAX): direct atomic scatter path ----
__global__ void pool_init_kernel(const float* __restrict__ x,
                                 float* __restrict__ out, int total, int pool) {
    int t = blockIdx.x * blockDim.x + threadIdx.x;
    if (t >= total) return;
    int m = t >> 4, cg = t & 15;
    const float4* xr = (const float4*)x + (size_t)m * (pool * (CH / 4)) + cg;
    float4 r = xr[0];
    for (int j = 1; j < pool; j++) {
        float4 a = xr[(size_t)j * (CH / 4)];
        r.x = fmaxf(r.x, a.x); r.y = fmaxf(r.y, a.y);
        r.z = fmaxf(r.z, a.z); r.w = fmaxf(r.w, a.w);
    }
    ((float4*)out)[t] = r;
}

__global__ void edge_scatter_kernel(const float* __restrict__ x,
                                    const int* __restrict__ src,
                                    const int* __restrict__ dst,
                                    const int* __restrict__ sel,
                                    const int* __restrict__ ks_ptr,
                                    float* __restrict__ out,
                                    int E, int pool, int sh) {
    int gwarp = (blockIdx.x * blockDim.x + threadIdx.x) >> 5;
    int lane = threadIdx.x & 31;
    int base = gwarp * 32;
    if (base >= E) return;
    int k = ks_ptr[0]; int thresh = k * k;
    int e = base + lane;
    int s = 0, d = 0; bool act = false;
    if (e < E) { int se = sel[e]; s = src[e]; d = dst[e]; act = (se < thresh); }
    unsigned mask = __ballot_sync(0xffffffffu, act);
    while (mask) {
        int l = __ffs(mask) - 1; mask &= mask - 1;
        int ss = __shfl_sync(0xffffffffu, s, l);
        int dd = __shfl_sync(0xffffffffu, d, l);
        int c = (sh >= 0) ? (dd >> sh) : (dd / pool);
        float2 v = ((const float2*)(x + (size_t)ss * CH))[lane];
        float* o = out + (size_t)c * CH + lane * 2;
        atomicMaxFloat(o, v.x);
        atomicMaxFloat(o + 1, v.y);
    }
}

extern "C" void kernel_launch(void* const* d_in, const int* in_sizes, int n_in,
                              void* d_out, int out_size) {
    const float* x   = (const float*)d_in[0];
    const int*   ei  = (const int*)d_in[1];   // [2,E]: src row then dst row
    const int*   sel = (const int*)d_in[2];
    const int*   ks  = (const int*)d_in[4];
    float* out = (float*)d_out;

    int E = in_sizes[1] / 2;
    int N = in_sizes[3];          // cluster array length
    int M = out_size / CH;
    int pool = N / M;
    int sh = -1;
    for (int b = 0; b < 31; b++) if ((1 << b) == pool) { sh = b; break; }

    const int* src = ei;
    const int* dst = ei + E;

    if (M <= M_MAX) {
        if ((E & 3) == 0) {
            int t = E / 4;
            bin_edges_vec_kernel<<<(t + 255) / 256, 256>>>(
                src, dst, sel, ks, E, pool, sh);
        } else {
            bin_edges_scalar_kernel<<<(E + 255) / 256, 256>>>(
                src, dst, sel, ks, E, pool, sh);
        }
        int threads = M * 32;
        int grid = (threads + 255) / 256;
        gather_half_kernel<<<grid, 256>>>(x, out, M, pool, 0,    0);
        gather_half_kernel<<<grid, 256>>>(x, out, M, pool, HALF, 1);
    } else {
        int totalA = M * (CH / 4);
        pool_init_kernel<<<(totalA + 255) / 256, 256>>>(x, out, totalA, pool);
        int warps = (E + 31) / 32;
        int threads = warps * 32;
        edge_scatter_kernel<<<(threads + 255) / 256, 256>>>(
            x, src, dst, sel, ks, out, E, pool, sh);
    }
}

// round 7
// speedup vs baseline: 1.2820x; 1.2820x over previous
#include <cuda_runtime.h>
#include <cstdint>

// SelMaxPool via bin + gather (single-phase, R4-proven structure):
//   pooled[m][c] = max( max_{j<pool} x[m*pool+j][c],
//                       max_{e active, dst[e]/pool == m} x[src[e]][c] )
// Pass 1: bin active edges' src ids per destination cluster (1 atomic/edge).
// Pass 2: one warp per cluster gathers & max-reduces (float2 per lane),
//         self-zeroes its counter for the next graph replay, and handles the
//         (normally empty) overflow list in-warp; the last block resets the
//         overflow counter via a done-ticket.

#define CH 64                 // channels (64 -> 32 float2 per warp)
#define M_MAX 131072          // max clusters supported by static scratch
#define CAP 96                // bin capacity per cluster (E[load] ~= 14)
#define OVF_CAP 131072

__device__ int g_cnt[M_MAX];
__device__ int g_bins[(size_t)M_MAX * CAP];
__device__ int g_ovf_cnt;
__device__ int g_ovf[2 * OVF_CAP];
__device__ unsigned g_done;

__device__ __forceinline__ void atomicMaxFloat(float* addr, float val) {
    if (val >= 0.0f) atomicMax((int*)addr, __float_as_int(val));
    else             atomicMin((unsigned int*)addr, __float_as_uint(val));
}

__global__ void bin_edges_kernel(const int* __restrict__ src,
                                 const int* __restrict__ dst,
                                 const int* __restrict__ sel,
                                 const int* __restrict__ ks_ptr,
                                 int E, int pool, int sh) {
    int e = blockIdx.x * blockDim.x + threadIdx.x;
    if (e >= E) return;
    int k = ks_ptr[0];
    if (sel[e] >= k * k) return;
    int d = dst[e];
    int c = (sh >= 0) ? (d >> sh) : (d / pool);
    int s = src[e];
    int slot = atomicAdd(&g_cnt[c], 1);
    if (slot < CAP) {
        g_bins[(size_t)c * CAP + slot] = s;
    } else {
        int o = atomicAdd(&g_ovf_cnt, 1);
        if (o < OVF_CAP) { g_ovf[2 * o] = s; g_ovf[2 * o + 1] = c; }
    }
}

__device__ __forceinline__ float2 fmax2(float2 a, float2 b) {
    a.x = fmaxf(a.x, b.x); a.y = fmaxf(a.y, b.y); return a;
}

// One warp per cluster. lane owns channels {2*lane, 2*lane+1}.
__global__ void gather_max_kernel(const float* __restrict__ x,
                                  float* __restrict__ out,
                                  int M, int pool) {
    int warp = (blockIdx.x * blockDim.x + threadIdx.x) >> 5;
    int lane = threadIdx.x & 31;
    const unsigned FULL = 0xffffffffu;

    if (warp < M) {
        const float2* __restrict__ xr = (const float2*)x;
        const int RS = CH / 2;  // 32 float2 per row

        // Own rows (sequential across warps -> fully coalesced stream of x).
        size_t rbase = (size_t)warp * pool * RS + lane;
        float2 acc = __ldg(&xr[rbase]);
        for (int j = 1; j < pool; j++)
            acc = fmax2(acc, __ldg(&xr[rbase + (size_t)j * RS]));

        // Bin list: prefetch up to CAP=96 src ids into 3 regs per lane,
        // then re-zero the counter for the next graph replay.
        int cnt = g_cnt[warp];
        if (lane == 0) g_cnt[warp] = 0;
        if (cnt > CAP) cnt = CAP;
        size_t bbase = (size_t)warp * CAP;
        int b0 = (lane      < cnt) ? g_bins[bbase + lane]      : 0;
        int b1 = (lane + 32 < cnt) ? g_bins[bbase + lane + 32] : 0;
        int b2 = (lane + 64 < cnt) ? g_bins[bbase + lane + 64] : 0;

        int chunks[3]; chunks[0] = b0; chunks[1] = b1; chunks[2] = b2;
        #pragma unroll
        for (int ch = 0; ch < 3; ch++) {
            int n = cnt - ch * 32;
            if (n <= 0) break;
            if (n > 32) n = 32;
            int b = chunks[ch];
            int i = 0;
            for (; i + 4 <= n; i += 4) {   // 4-way MLP on random row gathers
                int s0 = __shfl_sync(FULL, b, i);
                int s1 = __shfl_sync(FULL, b, i + 1);
                int s2 = __shfl_sync(FULL, b, i + 2);
                int s3 = __shfl_sync(FULL, b, i + 3);
                float2 v0 = __ldg(&xr[(size_t)s0 * RS + lane]);
                float2 v1 = __ldg(&xr[(size_t)s1 * RS + lane]);
                float2 v2 = __ldg(&xr[(size_t)s2 * RS + lane]);
                float2 v3 = __ldg(&xr[(size_t)s3 * RS + lane]);
                acc = fmax2(acc, fmax2(fmax2(v0, v1), fmax2(v2, v3)));
            }
            for (; i < n; i++) {
                int s0 = __shfl_sync(FULL, b, i);
                acc = fmax2(acc, __ldg(&xr[(size_t)s0 * RS + lane]));
            }
        }

        // Overflow (normally empty): each warp picks up its own entries.
        int novf = g_ovf_cnt;
        if (novf > OVF_CAP) novf = OVF_CAP;
        for (int i = 0; i < novf; i++) {
            if (g_ovf[2 * i + 1] == warp) {
                int s = g_ovf[2 * i];
                acc = fmax2(acc, __ldg(&xr[(size_t)s * RS + lane]));
            }
        }

        ((float2*)out)[(size_t)warp * RS + lane] = acc;
    }

    // Last finished block resets the overflow counter (all reads are done).
    __syncthreads();
    if (threadIdx.x == 0) {
        __threadfence();
        unsigned t = atomicAdd(&g_done, 1);
        if (t == gridDim.x - 1) {
            g_ovf_cnt = 0;
            g_done = 0;
            __threadfence();
        }
    }
}

// ---- Fallback (M > M_MAX): direct atomic scatter path ----
__global__ void pool_init_kernel(const float* __restrict__ x,
                                 float* __restrict__ out, int total, int pool) {
    int t = blockIdx.x * blockDim.x + threadIdx.x;
    if (t >= total) return;
    int m = t >> 4, cg = t & 15;
    const float4* xr = (const float4*)x + (size_t)m * (pool * (CH / 4)) + cg;
    float4 r = xr[0];
    for (int j = 1; j < pool; j++) {
        float4 a = xr[(size_t)j * (CH / 4)];
        r.x = fmaxf(r.x, a.x); r.y = fmaxf(r.y, a.y);
        r.z = fmaxf(r.z, a.z); r.w = fmaxf(r.w, a.w);
    }
    ((float4*)out)[t] = r;
}

__global__ void edge_scatter_kernel(const float* __restrict__ x,
                                    const int* __restrict__ src,
                                    const int* __restrict__ dst,
                                    const int* __restrict__ sel,
                                    const int* __restrict__ ks_ptr,
                                    float* __restrict__ out,
                                    int E, int pool, int sh) {
    int gwarp = (blockIdx.x * blockDim.x + threadIdx.x) >> 5;
    int lane = threadIdx.x & 31;
    int base = gwarp * 32;
    if (base >= E) return;
    int k = ks_ptr[0]; int thresh = k * k;
    int e = base + lane;
    int s = 0, d = 0; bool act = false;
    if (e < E) { int se = sel[e]; s = src[e]; d = dst[e]; act = (se < thresh); }
    unsigned mask = __ballot_sync(0xffffffffu, act);
    while (mask) {
        int l = __ffs(mask) - 1; mask &= mask - 1;
        int ss = __shfl_sync(0xffffffffu, s, l);
        int dd = __shfl_sync(0xffffffffu, d, l);
        int c = (sh >= 0) ? (dd >> sh) : (dd / pool);
        float2 v = ((const float2*)(x + (size_t)ss * CH))[lane];
        float* o = out + (size_t)c * CH + lane * 2;
        atomicMaxFloat(o, v.x);
        atomicMaxFloat(o + 1, v.y);
    }
}

extern "C" void kernel_launch(void* const* d_in, const int* in_sizes, int n_in,
                              void* d_out, int out_size) {
    const float* x   = (const float*)d_in[0];
    const int*   ei  = (const int*)d_in[1];   // [2,E]: src row then dst row
    const int*   sel = (const int*)d_in[2];
    const int*   ks  = (const int*)d_in[4];
    float* out = (float*)d_out;

    int E = in_sizes[1] / 2;
    int N = in_sizes[3];          // cluster array length
    int M = out_size / CH;
    int pool = N / M;
    int sh = -1;
    for (int b = 0; b < 31; b++) if ((1 << b) == pool) { sh = b; break; }

    const int* src = ei;
    const int* dst = ei + E;

    if (M <= M_MAX) {
        bin_edges_kernel<<<(E + 255) / 256, 256>>>(src, dst, sel, ks, E, pool, sh);
        int threads = M * 32;
        gather_max_kernel<<<(threads + 255) / 256, 256>>>(x, out, M, pool);
    } else {
        int totalA = M * (CH / 4);
        pool_init_kernel<<<(totalA + 255) / 256, 256>>>(x, out, totalA, pool);
        int warps = (E + 31) / 32;
        int threads = warps * 32;
        edge_scatter_kernel<<<(threads + 255) / 256, 256>>>(
            x, src, dst, sel, ks, out, E, pool, sh);
    }
}

// round 9
// speedup vs baseline: 5.6995x; 4.4458x over previous
#include <cuda_runtime.h>
#include <cstdint>

// SelMaxPool via bin + gather (R4 structure, clamped 8-deep gather batches):
//   pooled[m][c] = max( max_{j<pool} x[m*pool+j][c],
//                       max_{e active, dst[e]/pool == m} x[src[e]][c] )
// zero -> bin -> gather -> overflow. The gather kernel is kept free of any
// scratch-maintenance side work (R5/R7 showed that poisons it).

#define CH 64                 // channels (64 -> 32 float2 per warp)
#define M_MAX 131072          // max clusters supported by static scratch
#define CAP 96                // bin capacity per cluster (E[load] ~= 14)
#define OVF_CAP 262144

__device__ int g_cnt[M_MAX];
__device__ int g_bins[(size_t)M_MAX * CAP];
__device__ int g_ovf_cnt;
__device__ int g_ovf[2 * OVF_CAP];

__device__ __forceinline__ void atomicMaxFloat(float* addr, float val) {
    if (val >= 0.0f) atomicMax((int*)addr, __float_as_int(val));
    else             atomicMin((unsigned int*)addr, __float_as_uint(val));
}

__global__ void zero_counts_kernel(int M) {
    int i = blockIdx.x * blockDim.x + threadIdx.x;
    if (i < M) g_cnt[i] = 0;
    if (i == 0) g_ovf_cnt = 0;
}

__global__ void bin_edges_kernel(const int* __restrict__ src,
                                 const int* __restrict__ dst,
                                 const int* __restrict__ sel,
                                 const int* __restrict__ ks_ptr,
                                 int E, int pool, int sh) {
    int e = blockIdx.x * blockDim.x + threadIdx.x;
    if (e >= E) return;
    int k = ks_ptr[0];
    if (sel[e] >= k * k) return;
    int d = dst[e];
    int c = (sh >= 0) ? (d >> sh) : (d / pool);
    int s = src[e];
    int slot = atomicAdd(&g_cnt[c], 1);
    if (slot < CAP) {
        g_bins[(size_t)c * CAP + slot] = s;
    } else {
        int o = atomicAdd(&g_ovf_cnt, 1);
        if (o < OVF_CAP) { g_ovf[2 * o] = s; g_ovf[2 * o + 1] = c; }
    }
}

__device__ __forceinline__ float2 fmax2(float2 a, float2 b) {
    a.x = fmaxf(a.x, b.x); a.y = fmaxf(a.y, b.y); return a;
}

// One warp per cluster. lane owns channels {2*lane, 2*lane+1}.
// Gathers are issued in uniform 8-deep batches; indices are clamped to
// n-1 (duplicate loads are harmless under max), so there is no serial tail.
__global__ void __launch_bounds__(256)
gather_max_kernel(const float* __restrict__ x,
                  float* __restrict__ out,
                  int M, int pool) {
    int warp = (blockIdx.x * blockDim.x + threadIdx.x) >> 5;
    int lane = threadIdx.x & 31;
    if (warp >= M) return;
    const unsigned FULL = 0xffffffffu;
    const float2* __restrict__ xr = (const float2*)x;
    const int RS = CH / 2;  // 32 float2 per row

    // Own rows (sequential across warps -> fully coalesced stream of x).
    size_t rbase = (size_t)warp * pool * RS + lane;
    float2 acc = __ldg(&xr[rbase]);
    for (int j = 1; j < pool; j++)
        acc = fmax2(acc, __ldg(&xr[rbase + (size_t)j * RS]));

    int cnt = g_cnt[warp];
    if (cnt > CAP) cnt = CAP;

    if (cnt > 0) {
        size_t bbase = (size_t)warp * CAP;
        int last = cnt - 1;
        // Clamped prefetch: every lane's slot index is valid.
        int b0 = g_bins[bbase + min(lane, last)];
        int b1 = (cnt > 32) ? g_bins[bbase + min(lane + 32, last)] : 0;
        int b2 = (cnt > 64) ? g_bins[bbase + min(lane + 64, last)] : 0;

        int chunks[3]; chunks[0] = b0; chunks[1] = b1; chunks[2] = b2;
        #pragma unroll
        for (int ch = 0; ch < 3; ch++) {
            int n = cnt - ch * 32;
            if (n <= 0) break;
            if (n > 32) n = 32;
            int b = chunks[ch];
            int nl = n - 1;
            int nb = (n + 7) & ~7;          // round up to multiple of 8
            for (int i = 0; i < nb; i += 8) {
                int s0 = __shfl_sync(FULL, b, min(i,     nl));
                int s1 = __shfl_sync(FULL, b, min(i + 1, nl));
                int s2 = __shfl_sync(FULL, b, min(i + 2, nl));
                int s3 = __shfl_sync(FULL, b, min(i + 3, nl));
                int s4 = __shfl_sync(FULL, b, min(i + 4, nl));
                int s5 = __shfl_sync(FULL, b, min(i + 5, nl));
                int s6 = __shfl_sync(FULL, b, min(i + 6, nl));
                int s7 = __shfl_sync(FULL, b, min(i + 7, nl));
                float2 v0 = __ldg(&xr[(size_t)s0 * RS + lane]);
                float2 v1 = __ldg(&xr[(size_t)s1 * RS + lane]);
                float2 v2 = __ldg(&xr[(size_t)s2 * RS + lane]);
                float2 v3 = __ldg(&xr[(size_t)s3 * RS + lane]);
                float2 v4 = __ldg(&xr[(size_t)s4 * RS + lane]);
                float2 v5 = __ldg(&xr[(size_t)s5 * RS + lane]);
                float2 v6 = __ldg(&xr[(size_t)s6 * RS + lane]);
                float2 v7 = __ldg(&xr[(size_t)s7 * RS + lane]);
                float2 m0 = fmax2(fmax2(v0, v1), fmax2(v2, v3));
                float2 m1 = fmax2(fmax2(v4, v5), fmax2(v6, v7));
                acc = fmax2(acc, fmax2(m0, m1));
            }
        }
    }

    ((float2*)out)[(size_t)warp * RS + lane] = acc;
}

// Rarely-run cleanup for bin overflow. Runs AFTER gather init of out.
__global__ void overflow_kernel(const float* __restrict__ x,
                                float* __restrict__ out) {
    int n = g_ovf_cnt; if (n > OVF_CAP) n = OVF_CAP;
    int warp = threadIdx.x >> 5;
    int lane = threadIdx.x & 31;
    const float2* xr = (const float2*)x;
    for (int i = warp; i < n; i += blockDim.x / 32) {
        int s = g_ovf[2 * i], c = g_ovf[2 * i + 1];
        float2 v = xr[(size_t)s * (CH / 2) + lane];
        float* o = out + (size_t)c * CH + lane * 2;
        atomicMaxFloat(o, v.x);
        atomicMaxFloat(o + 1, v.y);
    }
}

// ---- Fallback (M > M_MAX): direct atomic scatter path ----
__global__ void pool_init_kernel(const float* __restrict__ x,
                                 float* __restrict__ out, int total, int pool) {
    int t = blockIdx.x * blockDim.x + threadIdx.x;
    if (t >= total) return;
    int m = t >> 4, cg = t & 15;
    const float4* xr = (const float4*)x + (size_t)m * (pool * (CH / 4)) + cg;
    float4 r = xr[0];
    for (int j = 1; j < pool; j++) {
        float4 a = xr[(size_t)j * (CH / 4)];
        r.x = fmaxf(r.x, a.x); r.y = fmaxf(r.y, a.y);
        r.z = fmaxf(r.z, a.z); r.w = fmaxf(r.w, a.w);
    }
    ((float4*)out)[t] = r;
}

__global__ void edge_scatter_kernel(const float* __restrict__ x,
                                    const int* __restrict__ src,
                                    const int* __restrict__ dst,
                                    const int* __restrict__ sel,
                                    const int* __restrict__ ks_ptr,
                                    float* __restrict__ out,
                                    int E, int pool, int sh) {
    int gwarp = (blockIdx.x * blockDim.x + threadIdx.x) >> 5;
    int lane = threadIdx.x & 31;
    int base = gwarp * 32;
    if (base >= E) return;
    int k = ks_ptr[0]; int thresh = k * k;
    int e = base + lane;
    int s = 0, d = 0; bool act = false;
    if (e < E) { int se = sel[e]; s = src[e]; d = dst[e]; act = (se < thresh); }
    unsigned mask = __ballot_sync(0xffffffffu, act);
    while (mask) {
        int l = __ffs(mask) - 1; mask &= mask - 1;
        int ss = __shfl_sync(0xffffffffu, s, l);
        int dd = __shfl_sync(0xffffffffu, d, l);
        int c = (sh >= 0) ? (dd >> sh) : (dd / pool);
        float2 v = ((const float2*)(x + (size_t)ss * CH))[lane];
        float* o = out + (size_t)c * CH + lane * 2;
        atomicMaxFloat(o, v.x);
        atomicMaxFloat(o + 1, v.y);
    }
}

extern "C" void kernel_launch(void* const* d_in, const int* in_sizes, int n_in,
                              void* d_out, int out_size) {
    const float* x   = (const float*)d_in[0];
    const int*   ei  = (const int*)d_in[1];   // [2,E]: src row then dst row
    const int*   sel = (const int*)d_in[2];
    const int*   ks  = (const int*)d_in[4];
    float* out = (float*)d_out;

    int E = in_sizes[1] / 2;
    int N = in_sizes[3];          // cluster array length
    int M = out_size / CH;
    int pool = N / M;
    int sh = -1;
    for (int b = 0; b < 31; b++) if ((1 << b) == pool) { sh = b; break; }

    const int* src = ei;
    const int* dst = ei + E;

    if (M <= M_MAX) {
        zero_counts_kernel<<<(M + 255) / 256, 256>>>(M);
        bin_edges_kernel<<<(E + 255) / 256, 256>>>(src, dst, sel, ks, E, pool, sh);
        int threads = M * 32;
        gather_max_kernel<<<(threads + 255) / 256, 256>>>(x, out, M, pool);
        overflow_kernel<<<1, 256>>>(x, out);
    } else {
        int totalA = M * (CH / 4);
        pool_init_kernel<<<(totalA + 255) / 256, 256>>>(x, out, totalA, pool);
        int warps = (E + 31) / 32;
        int threads = warps * 32;
        edge_scatter_kernel<<<(threads + 255) / 256, 256>>>(
            x, src, dst, sel, ks, out, E, pool, sh);
    }
}